// round 1
// baseline (speedup 1.0000x reference)
#include <cuda_runtime.h>
#include <math.h>

#define N_NODESC 20000
#define WINDOWC  8
#define N_BIGC   160000
#define IN_CC    8
#define HIDC     64
#define E_MAIN   1600000
#define E_DECC   500000
#define DHC      143
#define PSTRIDE  144

// ---------------- scratch (static device globals; no allocation) ----------------
__device__ float g_dis[N_BIGC];
__device__ float g_norm[E_MAIN];
__device__ float g_h[N_BIGC * HIDC];          // GEMM out / relu out (reused)
__device__ float g_agg[N_BIGC * HIDC];
__device__ float g_Xc[N_BIGC * 2 * HIDC];     // [n,128] = concat(h1,h2)
__device__ float g_gates[N_BIGC * 4 * HIDC];  // [n,256] input transforms (reused lstm1/2)
__device__ float g_y1[N_BIGC * HIDC];         // lstm1 outputs all t
__device__ float g_h2f[N_NODESC * HIDC];      // lstm2 final hidden
__device__ float g_emb[N_NODESC * DHC];
__device__ float g_Ps[N_NODESC * PSTRIDE];
__device__ float g_Pt[N_NODESC * PSTRIDE];
__device__ float g_stats[128];
__device__ float g_bnp[128];

// ---------------- small utility kernels ----------------
__global__ void k_zero(float* p, int n) {
    int i = blockIdx.x * blockDim.x + threadIdx.x;
    if (i < n) p[i] = 0.f;
}

__global__ void k_deg(const int* __restrict__ ei, const float* __restrict__ ea) {
    int i = blockIdx.x * blockDim.x + threadIdx.x;
    if (i < E_MAIN) atomicAdd(&g_dis[ei[E_MAIN + i]], ea[i]);
}

__global__ void k_dis() {
    int i = blockIdx.x * blockDim.x + threadIdx.x;
    if (i < N_BIGC) g_dis[i] = rsqrtf(g_dis[i] + 1.0f);  // + self-loop weight 1; deg >= 1
}

__global__ void k_norm(const int* __restrict__ ei, const float* __restrict__ ea) {
    int i = blockIdx.x * blockDim.x + threadIdx.x;
    if (i < E_MAIN) g_norm[i] = g_dis[ei[i]] * ea[i] * g_dis[ei[E_MAIN + i]];
}

// agg init with self-loop term: agg[n,:] = dis[n]^2 * h[n,:]
__global__ void k_selfinit() {
    int i = blockIdx.x * blockDim.x + threadIdx.x;
    if (i < N_BIGC * HIDC) {
        float d = g_dis[i >> 6];
        g_agg[i] = d * d * g_h[i];
    }
}

// scatter: 16 threads / edge, float4 gather of h[row], atomic adds into agg[col]
__global__ void k_scatter(const int* __restrict__ ei) {
    int t = blockIdx.x * blockDim.x + threadIdx.x;
    if (t >= E_MAIN * 16) return;
    int e = t >> 4, q = t & 15;
    float nv = g_norm[e];
    const float4* h4 = (const float4*)g_h;
    float4 v = h4[(size_t)ei[e] * 16 + q];
    float* a = g_agg + (size_t)ei[E_MAIN + e] * 64 + q * 4;
    atomicAdd(a + 0, nv * v.x);
    atomicAdd(a + 1, nv * v.y);
    atomicAdd(a + 2, nv * v.z);
    atomicAdd(a + 3, nv * v.w);
}

// y = relu(agg + bias); accumulate per-column sum & sumsq.  160000 % 256 == 0.
__global__ void k_brs(const float* __restrict__ bias) {
    __shared__ float ss[256], sq[256];
    int c = threadIdx.x & 63, rg = threadIdx.x >> 6;
    int base = blockIdx.x * 256;
    float bc = bias[c];
    float s = 0.f, s2 = 0.f;
    for (int j = 0; j < 64; j++) {
        int r = base + rg + j * 4;
        float v = g_agg[(size_t)r * 64 + c] + bc;
        v = fmaxf(v, 0.f);
        g_h[(size_t)r * 64 + c] = v;
        s += v; s2 += v * v;
    }
    ss[threadIdx.x] = s; sq[threadIdx.x] = s2;
    __syncthreads();
    if (rg == 0) {
        float a = ss[c] + ss[64 + c] + ss[128 + c] + ss[192 + c];
        float b = sq[c] + sq[64 + c] + sq[128 + c] + sq[192 + c];
        atomicAdd(&g_stats[c], a);
        atomicAdd(&g_stats[64 + c], b);
    }
}

__global__ void k_bnfinal(const float* __restrict__ gam, const float* __restrict__ bet) {
    int c = threadIdx.x;
    if (c < 64) {
        float inv_n = 1.f / (float)N_BIGC;
        float m = g_stats[c] * inv_n;
        float var = g_stats[64 + c] * inv_n - m * m;
        float a = rsqrtf(var + 1e-5f) * gam[c];
        g_bnp[c] = a;
        g_bnp[64 + c] = bet[c] - m * a;
    }
}

// apply BN into Xc[:, off:off+64]
__global__ void k_bnapply(int off) {
    int i = blockIdx.x * blockDim.x + threadIdx.x;
    if (i < N_BIGC * HIDC) {
        int c = i & 63, r = i >> 6;
        g_Xc[(size_t)r * 128 + off + c] = g_h[i] * g_bnp[c] + g_bnp[64 + c];
    }
}

// ---------------- SGEMM: C[M,N] = A[M,K] @ B (+bias1+bias2) ----------------
// BT=0: B is [K,N] (B[k*ldb+n]);  BT=1: B is [N,K] (B[n*ldb+k], i.e. A@B^T)
template <int BT>
__global__ void k_sgemm(const float* __restrict__ A, const float* __restrict__ B,
                        const float* __restrict__ bias1, const float* __restrict__ bias2,
                        float* __restrict__ C, int M, int N, int K,
                        int lda, int ldb, int ldc) {
    __shared__ float As[8][132];
    __shared__ float Bs[8][132];
    int tx = threadIdx.x, ty = threadIdx.y;       // 16 x 16
    int tid = ty * 16 + tx;
    int rowBase = blockIdx.y * 128, colBase = blockIdx.x * 128;
    float acc[8][8];
#pragma unroll
    for (int i = 0; i < 8; i++)
#pragma unroll
        for (int j = 0; j < 8; j++) acc[i][j] = 0.f;

    for (int k0 = 0; k0 < K; k0 += 8) {
#pragma unroll
        for (int q = 0; q < 4; q++) {
            int idx = q * 256 + tid;
            int r = idx >> 3, kk = idx & 7;
            int gr = rowBase + r, gk = k0 + kk;
            As[kk][r] = (gr < M && gk < K) ? A[(size_t)gr * lda + gk] : 0.f;
        }
        if (BT) {
#pragma unroll
            for (int q = 0; q < 4; q++) {
                int idx = q * 256 + tid;
                int cc = idx >> 3, kk = idx & 7;
                int gc = colBase + cc, gk = k0 + kk;
                Bs[kk][cc] = (gc < N && gk < K) ? B[(size_t)gc * ldb + gk] : 0.f;
            }
        } else {
#pragma unroll
            for (int q = 0; q < 4; q++) {
                int idx = q * 256 + tid;
                int cc = idx & 127, kk = idx >> 7;
                int gc = colBase + cc, gk = k0 + kk;
                Bs[kk][cc] = (gc < N && gk < K) ? B[(size_t)gk * ldb + gc] : 0.f;
            }
        }
        __syncthreads();
#pragma unroll
        for (int kk = 0; kk < 8; kk++) {
            float a[8], b[8];
            *(float4*)(a)     = *(const float4*)&As[kk][ty * 4];
            *(float4*)(a + 4) = *(const float4*)&As[kk][64 + ty * 4];
            *(float4*)(b)     = *(const float4*)&Bs[kk][tx * 4];
            *(float4*)(b + 4) = *(const float4*)&Bs[kk][64 + tx * 4];
#pragma unroll
            for (int i = 0; i < 8; i++)
#pragma unroll
                for (int j = 0; j < 8; j++) acc[i][j] += a[i] * b[j];
        }
        __syncthreads();
    }

    float bv[8];
#pragma unroll
    for (int j = 0; j < 8; j++) {
        int gc = colBase + ((j < 4) ? (tx * 4 + j) : (64 + tx * 4 + j - 4));
        float b = 0.f;
        if (gc < N) {
            if (bias1) b += bias1[gc];
            if (bias2) b += bias2[gc];
        }
        bv[j] = b;
    }
#pragma unroll
    for (int i = 0; i < 8; i++) {
        int gr = rowBase + ((i < 4) ? (ty * 4 + i) : (64 + ty * 4 + i - 4));
        if (gr < M) {
#pragma unroll
            for (int j = 0; j < 8; j++) {
                int gc = colBase + ((j < 4) ? (tx * 4 + j) : (64 + tx * 4 + j - 4));
                if (gc < N) C[(size_t)gr * ldc + gc] = acc[i][j] + bv[j];
            }
        }
    }
}

// ---------------- fused LSTM recurrence (all 8 timesteps) ----------------
// gates: [8*nrows, 256] precomputed x@Wih^T + bih + bhh. Rows independent.
// block: (64,4) threads, 64 rows per block. Whh + double-buffered h in dyn smem.
__global__ void k_lstm(const float* __restrict__ gates, const float* __restrict__ Whh,
                       float* __restrict__ y, float* __restrict__ hfinal, int nrows) {
    extern __shared__ float sm[];
    float* sW = sm;                 // [256][68] gate-major, padded
    float* hb = sm + 256 * 68;      // [2][64][68]
    int tx = threadIdx.x, ty = threadIdx.y;
    int tid = ty * 64 + tx;
    for (int idx = tid; idx < 256 * 64; idx += 256) {
        int g = idx >> 6, k = idx & 63;
        sW[g * 68 + k] = Whh[idx];
    }
    for (int idx = tid; idx < 2 * 64 * 68; idx += 256) hb[idx] = 0.f;
    __syncthreads();

    int row0 = blockIdx.x * 64;
    float cst[16];
#pragma unroll
    for (int i = 0; i < 16; i++) cst[i] = 0.f;
    int cur = 0;

    for (int t = 0; t < 8; t++) {
        const float* gt = gates + (size_t)t * nrows * 256;
        const float* hbc = hb + cur * 64 * 68;
        float* hbn = hb + (cur ^ 1) * 64 * 68;
#pragma unroll
        for (int ch = 0; ch < 4; ch++) {
            int lr0 = ty * 16 + ch * 4;
            float ai[4], af[4], ag[4], ao[4];
#pragma unroll
            for (int r = 0; r < 4; r++) {
                int grow = row0 + lr0 + r;
                if (grow < nrows) {
                    const float* gp = gt + (size_t)grow * 256;
                    ai[r] = gp[tx]; af[r] = gp[64 + tx];
                    ag[r] = gp[128 + tx]; ao[r] = gp[192 + tx];
                } else { ai[r] = af[r] = ag[r] = ao[r] = 0.f; }
            }
#pragma unroll
            for (int k0 = 0; k0 < 64; k0 += 4) {
                float4 wi = *(const float4*)&sW[(size_t)tx * 68 + k0];
                float4 wf = *(const float4*)&sW[(size_t)(64 + tx) * 68 + k0];
                float4 wg = *(const float4*)&sW[(size_t)(128 + tx) * 68 + k0];
                float4 wo = *(const float4*)&sW[(size_t)(192 + tx) * 68 + k0];
#pragma unroll
                for (int r = 0; r < 4; r++) {
                    float4 h4 = *(const float4*)&hbc[(size_t)(lr0 + r) * 68 + k0];
                    ai[r] += h4.x * wi.x + h4.y * wi.y + h4.z * wi.z + h4.w * wi.w;
                    af[r] += h4.x * wf.x + h4.y * wf.y + h4.z * wf.z + h4.w * wf.w;
                    ag[r] += h4.x * wg.x + h4.y * wg.y + h4.z * wg.z + h4.w * wg.w;
                    ao[r] += h4.x * wo.x + h4.y * wo.y + h4.z * wo.z + h4.w * wo.w;
                }
            }
#pragma unroll
            for (int r = 0; r < 4; r++) {
                int grow = row0 + lr0 + r;
                float ig = 1.f / (1.f + expf(-ai[r]));
                float fg = 1.f / (1.f + expf(-af[r]));
                float gg = tanhf(ag[r]);
                float og = 1.f / (1.f + expf(-ao[r]));
                float c = fg * cst[ch * 4 + r] + ig * gg;
                cst[ch * 4 + r] = c;
                float h = og * tanhf(c);
                hbn[(size_t)(lr0 + r) * 68 + tx] = h;
                if (grow < nrows) {
                    if (y) y[((size_t)t * nrows + grow) * 64 + tx] = h;
                    if (t == 7 && hfinal) hfinal[(size_t)grow * 64 + tx] = h;
                }
            }
        }
        cur ^= 1;
        __syncthreads();
    }
}

// ---------------- node embedding assembly ----------------
__global__ void k_emb(const float* __restrict__ x) {
    int i = blockIdx.x * blockDim.x + threadIdx.x;
    if (i >= N_NODESC * DHC) return;
    int b = i / DHC, j = i - b * DHC;
    float v;
    if (j < 64)       v = g_y1[((size_t)7 * N_NODESC + b) * 64 + j];   // H1 = lstm1 final h
    else if (j < 128) v = g_h2f[(size_t)b * 64 + (j - 64)];            // H2
    else if (j < 136) v = x[(size_t)b * 8 + (j - 128)];                // S: t=0 full feats
    else { int t = j - 135; v = x[((size_t)t * N_NODESC + b) * 8 + 7]; } // S: t=1..7 last chan
    g_emb[i] = v;
}

// ---------------- edge decoder: warp per edge ----------------
__global__ void k_edge(const int* __restrict__ ewi, const float* __restrict__ dWb,
                       const float* __restrict__ dbb, float* __restrict__ out) {
    __shared__ float sw[144];
    if (threadIdx.x < 143) sw[threadIdx.x] = dWb[threadIdx.x];
    __syncthreads();
    int warp = (blockIdx.x * blockDim.x + threadIdx.x) >> 5;
    int lane = threadIdx.x & 31;
    if (warp >= E_DECC) return;
    int s = ewi[warp], tg = ewi[E_DECC + warp];
    const float* ps = g_Ps + (size_t)s * PSTRIDE;
    const float* pt = g_Pt + (size_t)tg * PSTRIDE;
    float acc = 0.f;
#pragma unroll
    for (int j = lane; j < 143; j += 32) {
        float v = ps[j] + pt[j];
        acc += fmaxf(v, 0.f) * sw[j];
    }
#pragma unroll
    for (int o = 16; o; o >>= 1) acc += __shfl_down_sync(0xffffffffu, acc, o);
    if (lane == 0) out[warp] = acc + dbb[0];
}

// ---------------- host ----------------
static void launch_sgemm(int bt, const float* A, const float* B, const float* b1,
                         const float* b2, float* C, int M, int N, int K,
                         int lda, int ldb, int ldc) {
    dim3 grid((N + 127) / 128, (M + 127) / 128), block(16, 16);
    if (bt) k_sgemm<1><<<grid, block>>>(A, B, b1, b2, C, M, N, K, lda, ldb, ldc);
    else    k_sgemm<0><<<grid, block>>>(A, B, b1, b2, C, M, N, K, lda, ldb, ldc);
}

extern "C" void kernel_launch(void* const* d_in, const int* in_sizes, int n_in,
                              void* d_out, int out_size) {
    // --- resolve inputs by size (robust to metadata vs signature ordering) ---
    const float *x = 0, *ea = 0;
    const int *ei = 0, *ewi = 0;
    const float* w[20] = {0};
    int wi = 0;
    for (int i = 0; i < n_in; i++) {
        int s = in_sizes[i];
        if      (s == N_BIGC * IN_CC) x   = (const float*)d_in[i];
        else if (s == E_MAIN)         ea  = (const float*)d_in[i];
        else if (s == 2 * E_MAIN)     ei  = (const int*)d_in[i];
        else if (s == 2 * E_DECC)     ewi = (const int*)d_in[i];
        else if (wi < 20)             w[wi++] = (const float*)d_in[i];
    }
    const float *W1 = w[0], *b1 = w[1], *g1 = w[2], *be1 = w[3];
    const float *W2 = w[4], *b2 = w[5], *g2 = w[6], *be2 = w[7];
    const float *Wih1 = w[8], *Whh1 = w[9], *bih1 = w[10], *bhh1 = w[11];
    const float *Wih2 = w[12], *Whh2 = w[13], *bih2 = w[14], *bhh2 = w[15];
    const float *dWa = w[16], *dba = w[17], *dWb = w[18], *dbb = w[19];

    float *p_dis, *p_stats, *p_h, *p_Xc, *p_gates, *p_y1, *p_h2f, *p_emb, *p_Ps, *p_Pt;
    cudaGetSymbolAddress((void**)&p_dis, g_dis);
    cudaGetSymbolAddress((void**)&p_stats, g_stats);
    cudaGetSymbolAddress((void**)&p_h, g_h);
    cudaGetSymbolAddress((void**)&p_Xc, g_Xc);
    cudaGetSymbolAddress((void**)&p_gates, g_gates);
    cudaGetSymbolAddress((void**)&p_y1, g_y1);
    cudaGetSymbolAddress((void**)&p_h2f, g_h2f);
    cudaGetSymbolAddress((void**)&p_emb, g_emb);
    cudaGetSymbolAddress((void**)&p_Ps, g_Ps);
    cudaGetSymbolAddress((void**)&p_Pt, g_Pt);

    const int lstm_smem = (256 * 68 + 2 * 64 * 68) * 4;  // 104448 B
    cudaFuncSetAttribute(k_lstm, cudaFuncAttributeMaxDynamicSharedMemorySize, lstm_smem);

    // --- graph normalization (shared by both GCN layers) ---
    k_zero<<<(N_BIGC + 255) / 256, 256>>>(p_dis, N_BIGC);
    k_deg<<<(E_MAIN + 255) / 256, 256>>>(ei, ea);
    k_dis<<<(N_BIGC + 255) / 256, 256>>>();
    k_norm<<<(E_MAIN + 255) / 256, 256>>>(ei, ea);

    const int NB64 = N_BIGC * HIDC;

    // --- GCN layer 1 ---
    k_zero<<<1, 128>>>(p_stats, 128);
    launch_sgemm(0, x, W1, 0, 0, p_h, N_BIGC, HIDC, IN_CC, IN_CC, HIDC, HIDC);
    k_selfinit<<<(NB64 + 255) / 256, 256>>>();
    k_scatter<<<(E_MAIN * 16 + 255) / 256, 256>>>(ei);
    k_brs<<<N_BIGC / 256, 256>>>(b1);
    k_bnfinal<<<1, 64>>>(g1, be1);
    k_bnapply<<<(NB64 + 255) / 256, 256>>>(0);

    // --- GCN layer 2 (input = Xc[:,0:64], lda=128) ---
    k_zero<<<1, 128>>>(p_stats, 128);
    launch_sgemm(0, p_Xc, W2, 0, 0, p_h, N_BIGC, HIDC, HIDC, 2 * HIDC, HIDC, HIDC);
    k_selfinit<<<(NB64 + 255) / 256, 256>>>();
    k_scatter<<<(E_MAIN * 16 + 255) / 256, 256>>>(ei);
    k_brs<<<N_BIGC / 256, 256>>>(b2);
    k_bnfinal<<<1, 64>>>(g2, be2);
    k_bnapply<<<(NB64 + 255) / 256, 256>>>(64);

    // --- LSTM 1: input transform for all t, then fused recurrence ---
    launch_sgemm(1, p_Xc, Wih1, bih1, bhh1, p_gates, N_BIGC, 4 * HIDC, 2 * HIDC,
                 2 * HIDC, 2 * HIDC, 4 * HIDC);
    {
        dim3 grid((N_NODESC + 63) / 64), block(64, 4);
        k_lstm<<<grid, block, lstm_smem>>>(p_gates, Whh1, p_y1, 0, N_NODESC);
    }

    // --- LSTM 2 ---
    launch_sgemm(1, p_y1, Wih2, bih2, bhh2, p_gates, N_BIGC, 4 * HIDC, HIDC,
                 HIDC, HIDC, 4 * HIDC);
    {
        dim3 grid((N_NODESC + 63) / 64), block(64, 4);
        k_lstm<<<grid, block, lstm_smem>>>(p_gates, Whh2, 0, p_h2f, N_NODESC);
    }

    // --- node embedding + per-node decoder projections ---
    k_emb<<<(N_NODESC * DHC + 255) / 256, 256>>>(x);
    launch_sgemm(0, p_emb, dWa, dba, 0, p_Ps, N_NODESC, DHC, DHC, DHC, DHC, PSTRIDE);
    launch_sgemm(0, p_emb, dWa + DHC * DHC, 0, 0, p_Pt, N_NODESC, DHC, DHC, DHC, DHC, PSTRIDE);

    // --- edge decoder (warp per edge) ---
    k_edge<<<(E_DECC * 32 + 255) / 256, 256>>>(ewi, dWb, dbb, (float*)d_out);
}

// round 2
// speedup vs baseline: 1.1629x; 1.1629x over previous
#include <cuda_runtime.h>
#include <math.h>

#define N_NODESC 20000
#define WINDOWC  8
#define N_BIGC   160000
#define IN_CC    8
#define HIDC     64
#define E_MAIN   1600000
#define E_DECC   500000
#define DHC      143
#define PSTRIDE  144

// ---------------- scratch (static device globals; no allocation) ----------------
__device__ float g_dis[N_BIGC];
__device__ float g_norm[E_MAIN];
__device__ float g_h[N_BIGC * HIDC];          // GEMM out / relu out (reused)
__device__ float g_agg[N_BIGC * HIDC];
__device__ float g_Xc[N_BIGC * 2 * HIDC];     // [n,128] = concat(h1,h2)
__device__ float g_gates[N_BIGC * 4 * HIDC];  // [n,256] input transforms (reused lstm1/2)
__device__ float g_y1[N_BIGC * HIDC];         // lstm1 outputs all t
__device__ float g_h2f[N_NODESC * HIDC];      // lstm2 final hidden
__device__ float g_emb[N_NODESC * DHC];
__device__ float g_Ps[N_NODESC * PSTRIDE];    // col 143 never written -> stays 0 (zero-init)
__device__ float g_Pt[N_NODESC * PSTRIDE];
__device__ float g_stats[128];
__device__ float g_bnp[128];

// ---------------- small utility kernels ----------------
__global__ void k_zero(float* p, int n) {
    int i = blockIdx.x * blockDim.x + threadIdx.x;
    if (i < n) p[i] = 0.f;
}

__global__ void k_deg(const int* __restrict__ ei, const float* __restrict__ ea) {
    int i = blockIdx.x * blockDim.x + threadIdx.x;
    if (i < E_MAIN) atomicAdd(&g_dis[ei[E_MAIN + i]], ea[i]);
}

__global__ void k_dis() {
    int i = blockIdx.x * blockDim.x + threadIdx.x;
    if (i < N_BIGC) g_dis[i] = rsqrtf(g_dis[i] + 1.0f);  // + self-loop weight 1; deg >= 1
}

__global__ void k_norm(const int* __restrict__ ei, const float* __restrict__ ea) {
    int i = blockIdx.x * blockDim.x + threadIdx.x;
    if (i < E_MAIN) g_norm[i] = g_dis[ei[i]] * ea[i] * g_dis[ei[E_MAIN + i]];
}

// scatter: 16 threads / edge, float4 gather of h[row], ONE red.global.add.v4 into agg[col]
__global__ void k_scatter(const int* __restrict__ ei) {
    int t = blockIdx.x * blockDim.x + threadIdx.x;
    if (t >= E_MAIN * 16) return;
    int e = t >> 4, q = t & 15;
    float nv = g_norm[e];
    const float4* h4 = (const float4*)g_h;
    float4 v = h4[(size_t)ei[e] * 16 + q];
    float4* a = (float4*)(g_agg + (size_t)ei[E_MAIN + e] * 64) + q;
    asm volatile("red.global.add.v4.f32 [%0], {%1,%2,%3,%4};"
                 :: "l"(a), "f"(nv * v.x), "f"(nv * v.y), "f"(nv * v.z), "f"(nv * v.w)
                 : "memory");
}

// y = relu(agg + bias); accumulate per-column sum & sumsq.  160000 % 256 == 0.
__global__ void k_brs(const float* __restrict__ bias) {
    __shared__ float ss[256], sq[256];
    int c = threadIdx.x & 63, rg = threadIdx.x >> 6;
    int base = blockIdx.x * 256;
    float bc = bias[c];
    float s = 0.f, s2 = 0.f;
    for (int j = 0; j < 64; j++) {
        int r = base + rg + j * 4;
        float v = g_agg[(size_t)r * 64 + c] + bc;
        v = fmaxf(v, 0.f);
        g_h[(size_t)r * 64 + c] = v;
        s += v; s2 += v * v;
    }
    ss[threadIdx.x] = s; sq[threadIdx.x] = s2;
    __syncthreads();
    if (rg == 0) {
        float a = ss[c] + ss[64 + c] + ss[128 + c] + ss[192 + c];
        float b = sq[c] + sq[64 + c] + sq[128 + c] + sq[192 + c];
        atomicAdd(&g_stats[c], a);
        atomicAdd(&g_stats[64 + c], b);
    }
}

__global__ void k_bnfinal(const float* __restrict__ gam, const float* __restrict__ bet) {
    int c = threadIdx.x;
    if (c < 64) {
        float inv_n = 1.f / (float)N_BIGC;
        float m = g_stats[c] * inv_n;
        float var = g_stats[64 + c] * inv_n - m * m;
        float a = rsqrtf(var + 1e-5f) * gam[c];
        g_bnp[c] = a;
        g_bnp[64 + c] = bet[c] - m * a;
    }
}

// apply BN into Xc[:, off:off+64]
__global__ void k_bnapply(int off) {
    int i = blockIdx.x * blockDim.x + threadIdx.x;
    if (i < N_BIGC * HIDC) {
        int c = i & 63, r = i >> 6;
        g_Xc[(size_t)r * 128 + off + c] = g_h[i] * g_bnp[c] + g_bnp[64 + c];
    }
}

// ---------------- SGEMM (generic): C[M,N] = A[M,K] @ B (+bias1+bias2) ----------------
// BT=0: B is [K,N];  BT=1: B is [N,K] (A@B^T)
template <int BT>
__global__ void k_sgemm(const float* __restrict__ A, const float* __restrict__ B,
                        const float* __restrict__ bias1, const float* __restrict__ bias2,
                        float* __restrict__ C, int M, int N, int K,
                        int lda, int ldb, int ldc) {
    __shared__ float As[8][132];
    __shared__ float Bs[8][132];
    int tx = threadIdx.x, ty = threadIdx.y;       // 16 x 16
    int tid = ty * 16 + tx;
    int rowBase = blockIdx.y * 128, colBase = blockIdx.x * 128;
    float acc[8][8];
#pragma unroll
    for (int i = 0; i < 8; i++)
#pragma unroll
        for (int j = 0; j < 8; j++) acc[i][j] = 0.f;

    for (int k0 = 0; k0 < K; k0 += 8) {
#pragma unroll
        for (int q = 0; q < 4; q++) {
            int idx = q * 256 + tid;
            int r = idx >> 3, kk = idx & 7;
            int gr = rowBase + r, gk = k0 + kk;
            As[kk][r] = (gr < M && gk < K) ? A[(size_t)gr * lda + gk] : 0.f;
        }
        if (BT) {
#pragma unroll
            for (int q = 0; q < 4; q++) {
                int idx = q * 256 + tid;
                int cc = idx >> 3, kk = idx & 7;
                int gc = colBase + cc, gk = k0 + kk;
                Bs[kk][cc] = (gc < N && gk < K) ? B[(size_t)gc * ldb + gk] : 0.f;
            }
        } else {
#pragma unroll
            for (int q = 0; q < 4; q++) {
                int idx = q * 256 + tid;
                int cc = idx & 127, kk = idx >> 7;
                int gc = colBase + cc, gk = k0 + kk;
                Bs[kk][cc] = (gc < N && gk < K) ? B[(size_t)gk * ldb + gc] : 0.f;
            }
        }
        __syncthreads();
#pragma unroll
        for (int kk = 0; kk < 8; kk++) {
            float a[8], b[8];
            *(float4*)(a)     = *(const float4*)&As[kk][ty * 4];
            *(float4*)(a + 4) = *(const float4*)&As[kk][64 + ty * 4];
            *(float4*)(b)     = *(const float4*)&Bs[kk][tx * 4];
            *(float4*)(b + 4) = *(const float4*)&Bs[kk][64 + tx * 4];
#pragma unroll
            for (int i = 0; i < 8; i++)
#pragma unroll
                for (int j = 0; j < 8; j++) acc[i][j] += a[i] * b[j];
        }
        __syncthreads();
    }

    float bv[8];
#pragma unroll
    for (int j = 0; j < 8; j++) {
        int gc = colBase + ((j < 4) ? (tx * 4 + j) : (64 + tx * 4 + j - 4));
        float b = 0.f;
        if (gc < N) {
            if (bias1) b += bias1[gc];
            if (bias2) b += bias2[gc];
        }
        bv[j] = b;
    }
#pragma unroll
    for (int i = 0; i < 8; i++) {
        int gr = rowBase + ((i < 4) ? (ty * 4 + i) : (64 + ty * 4 + i - 4));
        if (gr < M) {
#pragma unroll
            for (int j = 0; j < 8; j++) {
                int gc = colBase + ((j < 4) ? (tx * 4 + j) : (64 + tx * 4 + j - 4));
                if (gc < N) C[(size_t)gr * ldc + gc] = acc[i][j] + bv[j];
            }
        }
    }
}

// ---------------- SGEMM N=64 + GCN epilogue: h = A@B; agg = dis^2 * h ----------------
// B is [K,64] row-major. Tile 128 rows x 64 cols, 8x4 per thread.
__global__ void k_sgemm64_gcn(const float* __restrict__ A, const float* __restrict__ B,
                              int M, int K, int lda) {
    __shared__ float As[8][132];
    __shared__ float Bs[8][68];
    int tx = threadIdx.x, ty = threadIdx.y;       // 16 x 16
    int tid = ty * 16 + tx;
    int rowBase = blockIdx.x * 128;
    float acc[8][4];
#pragma unroll
    for (int i = 0; i < 8; i++)
#pragma unroll
        for (int j = 0; j < 4; j++) acc[i][j] = 0.f;

    for (int k0 = 0; k0 < K; k0 += 8) {
#pragma unroll
        for (int q = 0; q < 4; q++) {
            int idx = q * 256 + tid;
            int r = idx >> 3, kk = idx & 7;
            int gr = rowBase + r, gk = k0 + kk;
            As[kk][r] = (gr < M && gk < K) ? A[(size_t)gr * lda + gk] : 0.f;
        }
#pragma unroll
        for (int q = 0; q < 2; q++) {
            int idx = q * 256 + tid;
            int cc = idx & 63, kk = idx >> 6;
            int gk = k0 + kk;
            Bs[kk][cc] = (gk < K) ? B[(size_t)gk * 64 + cc] : 0.f;
        }
        __syncthreads();
#pragma unroll
        for (int kk = 0; kk < 8; kk++) {
            float a[8], b[4];
            *(float4*)(a)     = *(const float4*)&As[kk][ty * 4];
            *(float4*)(a + 4) = *(const float4*)&As[kk][64 + ty * 4];
            *(float4*)(b)     = *(const float4*)&Bs[kk][tx * 4];
#pragma unroll
            for (int i = 0; i < 8; i++)
#pragma unroll
                for (int j = 0; j < 4; j++) acc[i][j] += a[i] * b[j];
        }
        __syncthreads();
    }

#pragma unroll
    for (int i = 0; i < 8; i++) {
        int gr = rowBase + ((i < 4) ? (ty * 4 + i) : (64 + ty * 4 + i - 4));
        if (gr < M) {
            float d = g_dis[gr];
            float d2 = d * d;
#pragma unroll
            for (int j = 0; j < 4; j++) {
                int gc = tx * 4 + j;
                float v = acc[i][j];
                g_h[(size_t)gr * 64 + gc] = v;
                g_agg[(size_t)gr * 64 + gc] = d2 * v;
            }
        }
    }
}

// ---------------- fused LSTM recurrence (all 8 timesteps) ----------------
__global__ void k_lstm(const float* __restrict__ gates, const float* __restrict__ Whh,
                       float* __restrict__ y, float* __restrict__ hfinal, int nrows) {
    extern __shared__ float sm[];
    float* sW = sm;                 // [256][68] gate-major, padded
    float* hb = sm + 256 * 68;      // [2][64][68]
    int tx = threadIdx.x, ty = threadIdx.y;
    int tid = ty * 64 + tx;
    for (int idx = tid; idx < 256 * 64; idx += 256) {
        int g = idx >> 6, k = idx & 63;
        sW[g * 68 + k] = Whh[idx];
    }
    for (int idx = tid; idx < 2 * 64 * 68; idx += 256) hb[idx] = 0.f;
    __syncthreads();

    int row0 = blockIdx.x * 64;
    float cst[16];
#pragma unroll
    for (int i = 0; i < 16; i++) cst[i] = 0.f;
    int cur = 0;

    for (int t = 0; t < 8; t++) {
        const float* gt = gates + (size_t)t * nrows * 256;
        const float* hbc = hb + cur * 64 * 68;
        float* hbn = hb + (cur ^ 1) * 64 * 68;
#pragma unroll
        for (int ch = 0; ch < 4; ch++) {
            int lr0 = ty * 16 + ch * 4;
            float ai[4], af[4], ag[4], ao[4];
#pragma unroll
            for (int r = 0; r < 4; r++) {
                int grow = row0 + lr0 + r;
                if (grow < nrows) {
                    const float* gp = gt + (size_t)grow * 256;
                    ai[r] = gp[tx]; af[r] = gp[64 + tx];
                    ag[r] = gp[128 + tx]; ao[r] = gp[192 + tx];
                } else { ai[r] = af[r] = ag[r] = ao[r] = 0.f; }
            }
#pragma unroll
            for (int k0 = 0; k0 < 64; k0 += 4) {
                float4 wi = *(const float4*)&sW[(size_t)tx * 68 + k0];
                float4 wf = *(const float4*)&sW[(size_t)(64 + tx) * 68 + k0];
                float4 wg = *(const float4*)&sW[(size_t)(128 + tx) * 68 + k0];
                float4 wo = *(const float4*)&sW[(size_t)(192 + tx) * 68 + k0];
#pragma unroll
                for (int r = 0; r < 4; r++) {
                    float4 h4 = *(const float4*)&hbc[(size_t)(lr0 + r) * 68 + k0];
                    ai[r] += h4.x * wi.x + h4.y * wi.y + h4.z * wi.z + h4.w * wi.w;
                    af[r] += h4.x * wf.x + h4.y * wf.y + h4.z * wf.z + h4.w * wf.w;
                    ag[r] += h4.x * wg.x + h4.y * wg.y + h4.z * wg.z + h4.w * wg.w;
                    ao[r] += h4.x * wo.x + h4.y * wo.y + h4.z * wo.z + h4.w * wo.w;
                }
            }
#pragma unroll
            for (int r = 0; r < 4; r++) {
                int grow = row0 + lr0 + r;
                float ig = 1.f / (1.f + expf(-ai[r]));
                float fg = 1.f / (1.f + expf(-af[r]));
                float gg = tanhf(ag[r]);
                float og = 1.f / (1.f + expf(-ao[r]));
                float c = fg * cst[ch * 4 + r] + ig * gg;
                cst[ch * 4 + r] = c;
                float h = og * tanhf(c);
                hbn[(size_t)(lr0 + r) * 68 + tx] = h;
                if (grow < nrows) {
                    if (y) y[((size_t)t * nrows + grow) * 64 + tx] = h;
                    if (t == 7 && hfinal) hfinal[(size_t)grow * 64 + tx] = h;
                }
            }
        }
        cur ^= 1;
        __syncthreads();
    }
}

// ---------------- node embedding assembly ----------------
__global__ void k_emb(const float* __restrict__ x) {
    int i = blockIdx.x * blockDim.x + threadIdx.x;
    if (i >= N_NODESC * DHC) return;
    int b = i / DHC, j = i - b * DHC;
    float v;
    if (j < 64)       v = g_y1[((size_t)7 * N_NODESC + b) * 64 + j];   // H1 = lstm1 final h
    else if (j < 128) v = g_h2f[(size_t)b * 64 + (j - 64)];            // H2
    else if (j < 136) v = x[(size_t)b * 8 + (j - 128)];                // S: t=0 full feats
    else { int t = j - 135; v = x[((size_t)t * N_NODESC + b) * 8 + 7]; } // S: t=1..7 last chan
    g_emb[i] = v;
}

// ---------------- edge decoder: warp per edge, float4 ----------------
__global__ void k_edge(const int* __restrict__ ewi, const float* __restrict__ dWb,
                       const float* __restrict__ dbb, float* __restrict__ out) {
    __shared__ float sw[PSTRIDE];
    if (threadIdx.x < PSTRIDE) sw[threadIdx.x] = (threadIdx.x < DHC) ? dWb[threadIdx.x] : 0.f;
    __syncthreads();
    int warp = (blockIdx.x * blockDim.x + threadIdx.x) >> 5;
    int lane = threadIdx.x & 31;
    if (warp >= E_DECC) return;
    int s = ewi[warp], tg = ewi[E_DECC + warp];
    const float4* ps = (const float4*)(g_Ps + (size_t)s * PSTRIDE);
    const float4* pt = (const float4*)(g_Pt + (size_t)tg * PSTRIDE);
    const float4* sw4 = (const float4*)sw;
    float acc = 0.f;
    {   // f4 indices: lane, and lane+32 for lane<4  (36 total)
        float4 a = ps[lane], b = pt[lane], w = sw4[lane];
        acc += fmaxf(a.x + b.x, 0.f) * w.x + fmaxf(a.y + b.y, 0.f) * w.y
             + fmaxf(a.z + b.z, 0.f) * w.z + fmaxf(a.w + b.w, 0.f) * w.w;
        if (lane < 4) {
            float4 a2 = ps[lane + 32], b2 = pt[lane + 32], w2 = sw4[lane + 32];
            acc += fmaxf(a2.x + b2.x, 0.f) * w2.x + fmaxf(a2.y + b2.y, 0.f) * w2.y
                 + fmaxf(a2.z + b2.z, 0.f) * w2.z + fmaxf(a2.w + b2.w, 0.f) * w2.w;
        }
    }
#pragma unroll
    for (int o = 16; o; o >>= 1) acc += __shfl_down_sync(0xffffffffu, acc, o);
    if (lane == 0) out[warp] = acc + dbb[0];
}

// ---------------- host ----------------
static void launch_sgemm(int bt, const float* A, const float* B, const float* b1,
                         const float* b2, float* C, int M, int N, int K,
                         int lda, int ldb, int ldc) {
    dim3 grid((N + 127) / 128, (M + 127) / 128), block(16, 16);
    if (bt) k_sgemm<1><<<grid, block>>>(A, B, b1, b2, C, M, N, K, lda, ldb, ldc);
    else    k_sgemm<0><<<grid, block>>>(A, B, b1, b2, C, M, N, K, lda, ldb, ldc);
}

extern "C" void kernel_launch(void* const* d_in, const int* in_sizes, int n_in,
                              void* d_out, int out_size) {
    // --- resolve inputs by size (robust to metadata vs signature ordering) ---
    const float *x = 0, *ea = 0;
    const int *ei = 0, *ewi = 0;
    const float* w[20] = {0};
    int wi = 0;
    for (int i = 0; i < n_in; i++) {
        int s = in_sizes[i];
        if      (s == N_BIGC * IN_CC) x   = (const float*)d_in[i];
        else if (s == E_MAIN)         ea  = (const float*)d_in[i];
        else if (s == 2 * E_MAIN)     ei  = (const int*)d_in[i];
        else if (s == 2 * E_DECC)     ewi = (const int*)d_in[i];
        else if (wi < 20)             w[wi++] = (const float*)d_in[i];
    }
    const float *W1 = w[0], *b1 = w[1], *g1 = w[2], *be1 = w[3];
    const float *W2 = w[4], *b2 = w[5], *g2 = w[6], *be2 = w[7];
    const float *Wih1 = w[8], *Whh1 = w[9], *bih1 = w[10], *bhh1 = w[11];
    const float *Wih2 = w[12], *Whh2 = w[13], *bih2 = w[14], *bhh2 = w[15];
    const float *dWa = w[16], *dba = w[17], *dWb = w[18], *dbb = w[19];

    float *p_dis, *p_stats, *p_Xc, *p_gates, *p_y1, *p_h2f, *p_emb, *p_Ps, *p_Pt;
    cudaGetSymbolAddress((void**)&p_dis, g_dis);
    cudaGetSymbolAddress((void**)&p_stats, g_stats);
    cudaGetSymbolAddress((void**)&p_Xc, g_Xc);
    cudaGetSymbolAddress((void**)&p_gates, g_gates);
    cudaGetSymbolAddress((void**)&p_y1, g_y1);
    cudaGetSymbolAddress((void**)&p_h2f, g_h2f);
    cudaGetSymbolAddress((void**)&p_emb, g_emb);
    cudaGetSymbolAddress((void**)&p_Ps, g_Ps);
    cudaGetSymbolAddress((void**)&p_Pt, g_Pt);

    const int lstm_smem = (256 * 68 + 2 * 64 * 68) * 4;  // 104448 B
    cudaFuncSetAttribute(k_lstm, cudaFuncAttributeMaxDynamicSharedMemorySize, lstm_smem);

    // --- graph normalization (shared by both GCN layers) ---
    k_zero<<<(N_BIGC + 255) / 256, 256>>>(p_dis, N_BIGC);
    k_deg<<<(E_MAIN + 255) / 256, 256>>>(ei, ea);
    k_dis<<<(N_BIGC + 255) / 256, 256>>>();
    k_norm<<<(E_MAIN + 255) / 256, 256>>>(ei, ea);

    const int NB64 = N_BIGC * HIDC;
    dim3 g64((N_BIGC + 127) / 128), b16(16, 16);

    // --- GCN layer 1 (GEMM fused with selfinit epilogue) ---
    k_zero<<<1, 128>>>(p_stats, 128);
    k_sgemm64_gcn<<<g64, b16>>>(x, W1, N_BIGC, IN_CC, IN_CC);
    k_scatter<<<(E_MAIN * 16 + 255) / 256, 256>>>(ei);
    k_brs<<<N_BIGC / 256, 256>>>(b1);
    k_bnfinal<<<1, 64>>>(g1, be1);
    k_bnapply<<<(NB64 + 255) / 256, 256>>>(0);

    // --- GCN layer 2 (input = Xc[:,0:64], lda=128) ---
    k_zero<<<1, 128>>>(p_stats, 128);
    k_sgemm64_gcn<<<g64, b16>>>(p_Xc, W2, N_BIGC, HIDC, 2 * HIDC);
    k_scatter<<<(E_MAIN * 16 + 255) / 256, 256>>>(ei);
    k_brs<<<N_BIGC / 256, 256>>>(b2);
    k_bnfinal<<<1, 64>>>(g2, be2);
    k_bnapply<<<(NB64 + 255) / 256, 256>>>(64);

    // --- LSTM 1: input transform for all t, then fused recurrence ---
    launch_sgemm(1, p_Xc, Wih1, bih1, bhh1, p_gates, N_BIGC, 4 * HIDC, 2 * HIDC,
                 2 * HIDC, 2 * HIDC, 4 * HIDC);
    {
        dim3 grid((N_NODESC + 63) / 64), block(64, 4);
        k_lstm<<<grid, block, lstm_smem>>>(p_gates, Whh1, p_y1, 0, N_NODESC);
    }

    // --- LSTM 2 ---
    launch_sgemm(1, p_y1, Wih2, bih2, bhh2, p_gates, N_BIGC, 4 * HIDC, HIDC,
                 HIDC, HIDC, 4 * HIDC);
    {
        dim3 grid((N_NODESC + 63) / 64), block(64, 4);
        k_lstm<<<grid, block, lstm_smem>>>(p_gates, Whh2, 0, p_h2f, N_NODESC);
    }

    // --- node embedding + per-node decoder projections ---
    k_emb<<<(N_NODESC * DHC + 255) / 256, 256>>>(x);
    launch_sgemm(0, p_emb, dWa, dba, 0, p_Ps, N_NODESC, DHC, DHC, DHC, DHC, PSTRIDE);
    launch_sgemm(0, p_emb, dWa + DHC * DHC, 0, 0, p_Pt, N_NODESC, DHC, DHC, DHC, DHC, PSTRIDE);

    // --- edge decoder (warp per edge, float4) ---
    k_edge<<<(E_DECC * 32 + 255) / 256, 256>>>(ewi, dWb, dbb, (float*)d_out);
}

// round 3
// speedup vs baseline: 1.2176x; 1.0470x over previous
#include <cuda_runtime.h>
#include <math.h>

#define N_NODESC 20000
#define WINDOWC  8
#define N_BIGC   160000
#define IN_CC    8
#define HIDC     64
#define E_MAIN   1600000
#define E_DECC   500000
#define DHC      143
#define PSTRIDE  144

// ---------------- scratch (static device globals; no allocation) ----------------
__device__ float g_dis[N_BIGC];
__device__ float g_norm[E_MAIN];
__device__ float g_h[N_BIGC * HIDC];
__device__ float g_agg[N_BIGC * HIDC];
__device__ float g_Xc[N_BIGC * 2 * HIDC];
__device__ float g_gates[N_BIGC * 4 * HIDC];
__device__ float g_y1[N_BIGC * HIDC];
__device__ float g_h2f[N_NODESC * HIDC];
__device__ float g_emb[N_NODESC * DHC];
__device__ float g_Ps[N_NODESC * PSTRIDE];    // col 143 never written -> stays 0
__device__ float g_Pt[N_NODESC * PSTRIDE];
__device__ float g_stats[128];
__device__ float g_bnp[128];

// ---------------- small utility kernels ----------------
__global__ void k_zero(float* p, int n) {
    int i = blockIdx.x * blockDim.x + threadIdx.x;
    if (i < n) p[i] = 0.f;
}

__global__ void k_deg(const int* __restrict__ ei, const float* __restrict__ ea) {
    int i = blockIdx.x * blockDim.x + threadIdx.x;
    if (i < E_MAIN) atomicAdd(&g_dis[ei[E_MAIN + i]], ea[i]);
}

__global__ void k_dis() {
    int i = blockIdx.x * blockDim.x + threadIdx.x;
    if (i < N_BIGC) g_dis[i] = rsqrtf(g_dis[i] + 1.0f);
}

__global__ void k_norm(const int* __restrict__ ei, const float* __restrict__ ea) {
    int i = blockIdx.x * blockDim.x + threadIdx.x;
    if (i < E_MAIN) g_norm[i] = g_dis[ei[i]] * ea[i] * g_dis[ei[E_MAIN + i]];
}

// scatter: 16 threads / edge, float4 gather, one red.global.add.v4
__global__ void k_scatter(const int* __restrict__ ei) {
    int t = blockIdx.x * blockDim.x + threadIdx.x;
    if (t >= E_MAIN * 16) return;
    int e = t >> 4, q = t & 15;
    float nv = g_norm[e];
    const float4* h4 = (const float4*)g_h;
    float4 v = h4[(size_t)ei[e] * 16 + q];
    float4* a = (float4*)(g_agg + (size_t)ei[E_MAIN + e] * 64) + q;
    asm volatile("red.global.add.v4.f32 [%0], {%1,%2,%3,%4};"
                 :: "l"(a), "f"(nv * v.x), "f"(nv * v.y), "f"(nv * v.z), "f"(nv * v.w)
                 : "memory");
}

// y = relu(agg + bias); accumulate per-column sum & sumsq
__global__ void k_brs(const float* __restrict__ bias) {
    __shared__ float ss[256], sq[256];
    int c = threadIdx.x & 63, rg = threadIdx.x >> 6;
    int base = blockIdx.x * 256;
    float bc = bias[c];
    float s = 0.f, s2 = 0.f;
    for (int j = 0; j < 64; j++) {
        int r = base + rg + j * 4;
        float v = g_agg[(size_t)r * 64 + c] + bc;
        v = fmaxf(v, 0.f);
        g_h[(size_t)r * 64 + c] = v;
        s += v; s2 += v * v;
    }
    ss[threadIdx.x] = s; sq[threadIdx.x] = s2;
    __syncthreads();
    if (rg == 0) {
        float a = ss[c] + ss[64 + c] + ss[128 + c] + ss[192 + c];
        float b = sq[c] + sq[64 + c] + sq[128 + c] + sq[192 + c];
        atomicAdd(&g_stats[c], a);
        atomicAdd(&g_stats[64 + c], b);
    }
}

__global__ void k_bnfinal(const float* __restrict__ gam, const float* __restrict__ bet) {
    int c = threadIdx.x;
    if (c < 64) {
        float inv_n = 1.f / (float)N_BIGC;
        float m = g_stats[c] * inv_n;
        float var = g_stats[64 + c] * inv_n - m * m;
        float a = rsqrtf(var + 1e-5f) * gam[c];
        g_bnp[c] = a;
        g_bnp[64 + c] = bet[c] - m * a;
    }
}

__global__ void k_bnapply(int off) {
    int i = blockIdx.x * blockDim.x + threadIdx.x;
    if (i < N_BIGC * HIDC) {
        int c = i & 63, r = i >> 6;
        g_Xc[(size_t)r * 128 + off + c] = g_h[i] * g_bnp[c] + g_bnp[64 + c];
    }
}

// ---------------- tf32 tensor-core GEMM ----------------
// C[M,N] = A[M,K] @ op(B) + bias1 + bias2
// BT=1: B is [N,K] row-major (A@B^T).  BT=0: B is [K,N] row-major.
// Block 256 thr (8 warps, 2x4), tile 128x128, K-chunk 32. mma m16n8k8 tf32.
__device__ __forceinline__ unsigned f2tf(float f) {
    unsigned u;
    asm("cvt.rna.tf32.f32 %0, %1;" : "=r"(u) : "f"(f));
    return u;
}

template <int BT>
__global__ void __launch_bounds__(256, 2)
k_tf32gemm(const float* __restrict__ A, const float* __restrict__ B,
           const float* __restrict__ bias1, const float* __restrict__ bias2,
           float* __restrict__ C, int M, int N, int K,
           int lda, int ldb, int ldc) {
    __shared__ unsigned As[128][33];
    __shared__ unsigned Bs[128][33];
    int tid = threadIdx.x;
    int warp = tid >> 5, lane = tid & 31;
    int wm = warp >> 2, wn = warp & 3;           // warp tile: rows wm*64, cols wn*32
    int rowBase = blockIdx.y * 128, colBase = blockIdx.x * 128;
    int lr = lane >> 2, lc = lane & 3;           // frag row/col pieces

    float c[4][4][4];
#pragma unroll
    for (int mi = 0; mi < 4; mi++)
#pragma unroll
        for (int ni = 0; ni < 4; ni++)
#pragma unroll
            for (int q = 0; q < 4; q++) c[mi][ni][q] = 0.f;

    for (int k0 = 0; k0 < K; k0 += 32) {
        // load A tile [128 x 32]
#pragma unroll
        for (int q = 0; q < 16; q++) {
            int idx = q * 256 + tid;
            int r = idx >> 5, kk = idx & 31;
            int gr = rowBase + r, gk = k0 + kk;
            float v = (gr < M && gk < K) ? A[(size_t)gr * lda + gk] : 0.f;
            As[r][kk] = f2tf(v);
        }
        if (BT) {  // B[n][k] -> Bs[n][k]
#pragma unroll
            for (int q = 0; q < 16; q++) {
                int idx = q * 256 + tid;
                int n = idx >> 5, kk = idx & 31;
                int gn = colBase + n, gk = k0 + kk;
                float v = (gn < N && gk < K) ? B[(size_t)gn * ldb + gk] : 0.f;
                Bs[n][kk] = f2tf(v);
            }
        } else {   // B[k][n] -> Bs[n][k]  (coalesced read over n; stride-33 store: conflict-free)
#pragma unroll
            for (int q = 0; q < 16; q++) {
                int idx = q * 256 + tid;
                int n = idx & 127, kk = idx >> 7;
                int gn = colBase + n, gk = k0 + kk;
                float v = (gn < N && gk < K) ? B[(size_t)gk * ldb + gn] : 0.f;
                Bs[n][kk] = f2tf(v);
            }
        }
        __syncthreads();

#pragma unroll
        for (int ks = 0; ks < 4; ks++) {
            int k8 = ks * 8;
            unsigned a[4][4], b[4][2];
#pragma unroll
            for (int mi = 0; mi < 4; mi++) {
                int r0 = wm * 64 + mi * 16 + lr;
                a[mi][0] = As[r0][k8 + lc];
                a[mi][1] = As[r0 + 8][k8 + lc];
                a[mi][2] = As[r0][k8 + lc + 4];
                a[mi][3] = As[r0 + 8][k8 + lc + 4];
            }
#pragma unroll
            for (int ni = 0; ni < 4; ni++) {
                int n0 = wn * 32 + ni * 8 + lr;
                b[ni][0] = Bs[n0][k8 + lc];
                b[ni][1] = Bs[n0][k8 + lc + 4];
            }
#pragma unroll
            for (int mi = 0; mi < 4; mi++)
#pragma unroll
                for (int ni = 0; ni < 4; ni++) {
                    asm volatile(
                        "mma.sync.aligned.m16n8k8.row.col.f32.tf32.tf32.f32 "
                        "{%0,%1,%2,%3}, {%4,%5,%6,%7}, {%8,%9}, {%0,%1,%2,%3};"
                        : "+f"(c[mi][ni][0]), "+f"(c[mi][ni][1]),
                          "+f"(c[mi][ni][2]), "+f"(c[mi][ni][3])
                        : "r"(a[mi][0]), "r"(a[mi][1]), "r"(a[mi][2]), "r"(a[mi][3]),
                          "r"(b[ni][0]), "r"(b[ni][1]));
                }
        }
        __syncthreads();
    }

    // epilogue
#pragma unroll
    for (int mi = 0; mi < 4; mi++) {
#pragma unroll
        for (int ni = 0; ni < 4; ni++) {
            int gr0 = rowBase + wm * 64 + mi * 16 + lr;
            int gc0 = colBase + wn * 32 + ni * 8 + lc * 2;
#pragma unroll
            for (int q = 0; q < 4; q++) {
                int gr = gr0 + (q >> 1) * 8;
                int gc = gc0 + (q & 1);
                if (gr < M && gc < N) {
                    float b = 0.f;
                    if (bias1) b += bias1[gc];
                    if (bias2) b += bias2[gc];
                    C[(size_t)gr * ldc + gc] = c[mi][ni][q] + b;
                }
            }
        }
    }
}

// ---------------- SGEMM N=64 + GCN epilogue: h = A@B; agg = dis^2 * h ----------------
__global__ void k_sgemm64_gcn(const float* __restrict__ A, const float* __restrict__ B,
                              int M, int K, int lda) {
    __shared__ float As[8][132];
    __shared__ float Bs[8][68];
    int tx = threadIdx.x, ty = threadIdx.y;       // 16 x 16
    int tid = ty * 16 + tx;
    int rowBase = blockIdx.x * 128;
    float acc[8][4];
#pragma unroll
    for (int i = 0; i < 8; i++)
#pragma unroll
        for (int j = 0; j < 4; j++) acc[i][j] = 0.f;

    for (int k0 = 0; k0 < K; k0 += 8) {
#pragma unroll
        for (int q = 0; q < 4; q++) {
            int idx = q * 256 + tid;
            int r = idx >> 3, kk = idx & 7;
            int gr = rowBase + r, gk = k0 + kk;
            As[kk][r] = (gr < M && gk < K) ? A[(size_t)gr * lda + gk] : 0.f;
        }
#pragma unroll
        for (int q = 0; q < 2; q++) {
            int idx = q * 256 + tid;
            int cc = idx & 63, kk = idx >> 6;
            int gk = k0 + kk;
            Bs[kk][cc] = (gk < K) ? B[(size_t)gk * 64 + cc] : 0.f;
        }
        __syncthreads();
#pragma unroll
        for (int kk = 0; kk < 8; kk++) {
            float a[8], b[4];
            *(float4*)(a)     = *(const float4*)&As[kk][ty * 4];
            *(float4*)(a + 4) = *(const float4*)&As[kk][64 + ty * 4];
            *(float4*)(b)     = *(const float4*)&Bs[kk][tx * 4];
#pragma unroll
            for (int i = 0; i < 8; i++)
#pragma unroll
                for (int j = 0; j < 4; j++) acc[i][j] += a[i] * b[j];
        }
        __syncthreads();
    }

#pragma unroll
    for (int i = 0; i < 8; i++) {
        int gr = rowBase + ((i < 4) ? (ty * 4 + i) : (64 + ty * 4 + i - 4));
        if (gr < M) {
            float d = g_dis[gr];
            float d2 = d * d;
#pragma unroll
            for (int j = 0; j < 4; j++) {
                int gc = tx * 4 + j;
                float v = acc[i][j];
                g_h[(size_t)gr * 64 + gc] = v;
                g_agg[(size_t)gr * 64 + gc] = d2 * v;
            }
        }
    }
}

// ---------------- fused LSTM recurrence (all 8 timesteps) ----------------
__global__ void k_lstm(const float* __restrict__ gates, const float* __restrict__ Whh,
                       float* __restrict__ y, float* __restrict__ hfinal, int nrows) {
    extern __shared__ float sm[];
    float* sW = sm;                 // [256][68] gate-major, padded
    float* hb = sm + 256 * 68;      // [2][64][68]
    int tx = threadIdx.x, ty = threadIdx.y;
    int tid = ty * 64 + tx;
    for (int idx = tid; idx < 256 * 64; idx += 256) {
        int g = idx >> 6, k = idx & 63;
        sW[g * 68 + k] = Whh[idx];
    }
    for (int idx = tid; idx < 2 * 64 * 68; idx += 256) hb[idx] = 0.f;
    __syncthreads();

    int row0 = blockIdx.x * 64;
    float cst[16];
#pragma unroll
    for (int i = 0; i < 16; i++) cst[i] = 0.f;
    int cur = 0;

    for (int t = 0; t < 8; t++) {
        const float* gt = gates + (size_t)t * nrows * 256;
        const float* hbc = hb + cur * 64 * 68;
        float* hbn = hb + (cur ^ 1) * 64 * 68;
#pragma unroll
        for (int ch = 0; ch < 4; ch++) {
            int lr0 = ty * 16 + ch * 4;
            float ai[4], af[4], ag[4], ao[4];
#pragma unroll
            for (int r = 0; r < 4; r++) {
                int grow = row0 + lr0 + r;
                if (grow < nrows) {
                    const float* gp = gt + (size_t)grow * 256;
                    ai[r] = gp[tx]; af[r] = gp[64 + tx];
                    ag[r] = gp[128 + tx]; ao[r] = gp[192 + tx];
                } else { ai[r] = af[r] = ag[r] = ao[r] = 0.f; }
            }
#pragma unroll
            for (int k0 = 0; k0 < 64; k0 += 4) {
                float4 wi = *(const float4*)&sW[(size_t)tx * 68 + k0];
                float4 wf = *(const float4*)&sW[(size_t)(64 + tx) * 68 + k0];
                float4 wg = *(const float4*)&sW[(size_t)(128 + tx) * 68 + k0];
                float4 wo = *(const float4*)&sW[(size_t)(192 + tx) * 68 + k0];
#pragma unroll
                for (int r = 0; r < 4; r++) {
                    float4 h4 = *(const float4*)&hbc[(size_t)(lr0 + r) * 68 + k0];
                    ai[r] += h4.x * wi.x + h4.y * wi.y + h4.z * wi.z + h4.w * wi.w;
                    af[r] += h4.x * wf.x + h4.y * wf.y + h4.z * wf.z + h4.w * wf.w;
                    ag[r] += h4.x * wg.x + h4.y * wg.y + h4.z * wg.z + h4.w * wg.w;
                    ao[r] += h4.x * wo.x + h4.y * wo.y + h4.z * wo.z + h4.w * wo.w;
                }
            }
#pragma unroll
            for (int r = 0; r < 4; r++) {
                int grow = row0 + lr0 + r;
                float ig = 1.f / (1.f + expf(-ai[r]));
                float fg = 1.f / (1.f + expf(-af[r]));
                float gg = tanhf(ag[r]);
                float og = 1.f / (1.f + expf(-ao[r]));
                float c = fg * cst[ch * 4 + r] + ig * gg;
                cst[ch * 4 + r] = c;
                float h = og * tanhf(c);
                hbn[(size_t)(lr0 + r) * 68 + tx] = h;
                if (grow < nrows) {
                    if (y) y[((size_t)t * nrows + grow) * 64 + tx] = h;
                    if (t == 7 && hfinal) hfinal[(size_t)grow * 64 + tx] = h;
                }
            }
        }
        cur ^= 1;
        __syncthreads();
    }
}

// ---------------- node embedding assembly ----------------
__global__ void k_emb(const float* __restrict__ x) {
    int i = blockIdx.x * blockDim.x + threadIdx.x;
    if (i >= N_NODESC * DHC) return;
    int b = i / DHC, j = i - b * DHC;
    float v;
    if (j < 64)       v = g_y1[((size_t)7 * N_NODESC + b) * 64 + j];
    else if (j < 128) v = g_h2f[(size_t)b * 64 + (j - 64)];
    else if (j < 136) v = x[(size_t)b * 8 + (j - 128)];
    else { int t = j - 135; v = x[((size_t)t * N_NODESC + b) * 8 + 7]; }
    g_emb[i] = v;
}

// ---------------- edge decoder: warp per edge, float4 ----------------
__global__ void k_edge(const int* __restrict__ ewi, const float* __restrict__ dWb,
                       const float* __restrict__ dbb, float* __restrict__ out) {
    __shared__ float sw[PSTRIDE];
    if (threadIdx.x < PSTRIDE) sw[threadIdx.x] = (threadIdx.x < DHC) ? dWb[threadIdx.x] : 0.f;
    __syncthreads();
    int warp = (blockIdx.x * blockDim.x + threadIdx.x) >> 5;
    int lane = threadIdx.x & 31;
    if (warp >= E_DECC) return;
    int s = ewi[warp], tg = ewi[E_DECC + warp];
    const float4* ps = (const float4*)(g_Ps + (size_t)s * PSTRIDE);
    const float4* pt = (const float4*)(g_Pt + (size_t)tg * PSTRIDE);
    const float4* sw4 = (const float4*)sw;
    float acc = 0.f;
    {
        float4 a = ps[lane], b = pt[lane], w = sw4[lane];
        acc += fmaxf(a.x + b.x, 0.f) * w.x + fmaxf(a.y + b.y, 0.f) * w.y
             + fmaxf(a.z + b.z, 0.f) * w.z + fmaxf(a.w + b.w, 0.f) * w.w;
        if (lane < 4) {
            float4 a2 = ps[lane + 32], b2 = pt[lane + 32], w2 = sw4[lane + 32];
            acc += fmaxf(a2.x + b2.x, 0.f) * w2.x + fmaxf(a2.y + b2.y, 0.f) * w2.y
                 + fmaxf(a2.z + b2.z, 0.f) * w2.z + fmaxf(a2.w + b2.w, 0.f) * w2.w;
        }
    }
#pragma unroll
    for (int o = 16; o; o >>= 1) acc += __shfl_down_sync(0xffffffffu, acc, o);
    if (lane == 0) out[warp] = acc + dbb[0];
}

// ---------------- host ----------------
extern "C" void kernel_launch(void* const* d_in, const int* in_sizes, int n_in,
                              void* d_out, int out_size) {
    const float *x = 0, *ea = 0;
    const int *ei = 0, *ewi = 0;
    const float* w[20] = {0};
    int wi = 0;
    for (int i = 0; i < n_in; i++) {
        int s = in_sizes[i];
        if      (s == N_BIGC * IN_CC) x   = (const float*)d_in[i];
        else if (s == E_MAIN)         ea  = (const float*)d_in[i];
        else if (s == 2 * E_MAIN)     ei  = (const int*)d_in[i];
        else if (s == 2 * E_DECC)     ewi = (const int*)d_in[i];
        else if (wi < 20)             w[wi++] = (const float*)d_in[i];
    }
    const float *W1 = w[0], *b1 = w[1], *g1 = w[2], *be1 = w[3];
    const float *W2 = w[4], *b2 = w[5], *g2 = w[6], *be2 = w[7];
    const float *Wih1 = w[8], *Whh1 = w[9], *bih1 = w[10], *bhh1 = w[11];
    const float *Wih2 = w[12], *Whh2 = w[13], *bih2 = w[14], *bhh2 = w[15];
    const float *dWa = w[16], *dba = w[17], *dWb = w[18], *dbb = w[19];

    float *p_dis, *p_stats, *p_Xc, *p_gates, *p_y1, *p_h2f, *p_emb, *p_Ps, *p_Pt;
    cudaGetSymbolAddress((void**)&p_dis, g_dis);
    cudaGetSymbolAddress((void**)&p_stats, g_stats);
    cudaGetSymbolAddress((void**)&p_Xc, g_Xc);
    cudaGetSymbolAddress((void**)&p_gates, g_gates);
    cudaGetSymbolAddress((void**)&p_y1, g_y1);
    cudaGetSymbolAddress((void**)&p_h2f, g_h2f);
    cudaGetSymbolAddress((void**)&p_emb, g_emb);
    cudaGetSymbolAddress((void**)&p_Ps, g_Ps);
    cudaGetSymbolAddress((void**)&p_Pt, g_Pt);

    const int lstm_smem = (256 * 68 + 2 * 64 * 68) * 4;  // 104448 B
    cudaFuncSetAttribute(k_lstm, cudaFuncAttributeMaxDynamicSharedMemorySize, lstm_smem);

    // --- graph normalization ---
    k_zero<<<(N_BIGC + 255) / 256, 256>>>(p_dis, N_BIGC);
    k_deg<<<(E_MAIN + 255) / 256, 256>>>(ei, ea);
    k_dis<<<(N_BIGC + 255) / 256, 256>>>();
    k_norm<<<(E_MAIN + 255) / 256, 256>>>(ei, ea);

    const int NB64 = N_BIGC * HIDC;
    dim3 g64((N_BIGC + 127) / 128), b16(16, 16);

    // --- GCN layer 1 ---
    k_zero<<<1, 128>>>(p_stats, 128);
    k_sgemm64_gcn<<<g64, b16>>>(x, W1, N_BIGC, IN_CC, IN_CC);
    k_scatter<<<(E_MAIN * 16 + 255) / 256, 256>>>(ei);
    k_brs<<<N_BIGC / 256, 256>>>(b1);
    k_bnfinal<<<1, 64>>>(g1, be1);
    k_bnapply<<<(NB64 + 255) / 256, 256>>>(0);

    // --- GCN layer 2 ---
    k_zero<<<1, 128>>>(p_stats, 128);
    k_sgemm64_gcn<<<g64, b16>>>(p_Xc, W2, N_BIGC, HIDC, 2 * HIDC);
    k_scatter<<<(E_MAIN * 16 + 255) / 256, 256>>>(ei);
    k_brs<<<N_BIGC / 256, 256>>>(b2);
    k_bnfinal<<<1, 64>>>(g2, be2);
    k_bnapply<<<(NB64 + 255) / 256, 256>>>(64);

    // --- LSTM 1: tf32 input-transform GEMM + fused recurrence ---
    {
        dim3 grid(2, (N_BIGC + 127) / 128);
        k_tf32gemm<1><<<grid, 256>>>(p_Xc, Wih1, bih1, bhh1, p_gates,
                                     N_BIGC, 4 * HIDC, 2 * HIDC,
                                     2 * HIDC, 2 * HIDC, 4 * HIDC);
        dim3 gl((N_NODESC + 63) / 64), bl(64, 4);
        k_lstm<<<gl, bl, lstm_smem>>>(p_gates, Whh1, p_y1, 0, N_NODESC);
    }

    // --- LSTM 2 ---
    {
        dim3 grid(2, (N_BIGC + 127) / 128);
        k_tf32gemm<1><<<grid, 256>>>(p_y1, Wih2, bih2, bhh2, p_gates,
                                     N_BIGC, 4 * HIDC, HIDC,
                                     HIDC, HIDC, 4 * HIDC);
        dim3 gl((N_NODESC + 63) / 64), bl(64, 4);
        k_lstm<<<gl, bl, lstm_smem>>>(p_gates, Whh2, 0, p_h2f, N_NODESC);
    }

    // --- node embedding + decoder projections (tf32) ---
    k_emb<<<(N_NODESC * DHC + 255) / 256, 256>>>(x);
    {
        dim3 grid((DHC + 127) / 128, (N_NODESC + 127) / 128);
        k_tf32gemm<0><<<grid, 256>>>(p_emb, dWa, dba, 0, p_Ps,
                                     N_NODESC, DHC, DHC, DHC, DHC, PSTRIDE);
        k_tf32gemm<0><<<grid, 256>>>(p_emb, dWa + DHC * DHC, 0, 0, p_Pt,
                                     N_NODESC, DHC, DHC, DHC, DHC, PSTRIDE);
    }

    // --- edge decoder ---
    k_edge<<<(E_DECC * 32 + 255) / 256, 256>>>(ewi, dWb, dbb, (float*)d_out);
}